// round 6
// baseline (speedup 1.0000x reference)
#include <cuda_runtime.h>
#include <cstdint>

#define NUM_DENSE 13
#define NUM_SPARSE 26
#define FEAT_NUM 40000
#define FL (NUM_SPARSE * FEAT_NUM + NUM_DENSE)   // 1040013
#define KDIM 64
#define BATCH 4096

// One block (64 threads) per batch row. Thread t owns V row k=t.
// sv_t = sum over active features of x_f * V[t, f]
// s2_t = sum over active features of (x_f * V[t, f])^2
// out[b] = w0 + sum_f x_f * w[f] + 0.5 * ( sum_t sv_t^2 - sum_t s2_t )
__global__ __launch_bounds__(64) void fm_layer_kernel(
    const float* __restrict__ dense,        // [BATCH, 13] f32
    const int* __restrict__ sparse,         // [BATCH, 26] int32 (JAX x64 disabled)
    const float* __restrict__ w0,           // [1]
    const float* __restrict__ w,            // [FL]
    const float* __restrict__ V,            // [64, FL]
    float* __restrict__ out)                // [BATCH]
{
    const int b = blockIdx.x;
    const int t = threadIdx.x;              // 0..63 == k index

    __shared__ int   cols[NUM_SPARSE];
    __shared__ float xd[NUM_DENSE];
    __shared__ float wsum[2];

    if (t < NUM_SPARSE) {
        int idx = sparse[b * NUM_SPARSE + t];
        cols[t] = idx + NUM_DENSE + FEAT_NUM * t;
    }
    if (t >= 32 && t < 32 + NUM_DENSE) {
        xd[t - 32] = dense[b * NUM_DENSE + (t - 32)];
    }
    __syncthreads();

    const float* __restrict__ Vrow = V + (size_t)t * (size_t)FL;

    // Front-batch all 26 strided gathers for max MLP.
    float vv[NUM_SPARSE];
#pragma unroll
    for (int j = 0; j < NUM_SPARSE; j++) {
        vv[j] = __ldg(&Vrow[cols[j]]);
    }

    float sv = 0.f, s2 = 0.f;
#pragma unroll
    for (int j = 0; j < NUM_SPARSE; j++) {
        sv += vv[j];
        s2 = fmaf(vv[j], vv[j], s2);
    }

    // Dense part: columns 0..12 of each V row (tiny, L2-hot).
#pragma unroll
    for (int d = 0; d < NUM_DENSE; d++) {
        float xv = xd[d] * __ldg(&Vrow[d]);
        sv += xv;
        s2 = fmaf(xv, xv, s2);
    }

    float part = 0.5f * fmaf(sv, sv, -s2);

    // First-order term, distributed across lanes.
    if (t < NUM_SPARSE) {
        part += __ldg(&w[cols[t]]);
    }
    if (t >= 32 && t < 32 + NUM_DENSE) {
        part += xd[t - 32] * __ldg(&w[t - 32]);
    }

    // Reduce 64 threads: warp shuffle, then 2-way shared combine.
#pragma unroll
    for (int off = 16; off > 0; off >>= 1) {
        part += __shfl_down_sync(0xFFFFFFFFu, part, off);
    }
    if ((t & 31) == 0) wsum[t >> 5] = part;
    __syncthreads();
    if (t == 0) {
        out[b] = w0[0] + wsum[0] + wsum[1];
    }
}

extern "C" void kernel_launch(void* const* d_in, const int* in_sizes, int n_in,
                              void* d_out, int out_size)
{
    const float* dense  = (const float*)d_in[0];      // 4096*13 f32
    const int*   sparse = (const int*)d_in[1];        // 4096*26 int32
    const float* w0     = (const float*)d_in[2];      // 1
    const float* w      = (const float*)d_in[3];      // 1040013
    const float* V      = (const float*)d_in[4];      // 64*1040013
    float*       out    = (float*)d_out;              // 4096

    fm_layer_kernel<<<BATCH, 64>>>(dense, sparse, w0, w, V, out);
}